// round 12
// baseline (speedup 1.0000x reference)
#include <cuda_runtime.h>
#include <cuda_bf16.h>
#include <cuda_fp16.h>
#include <math_constants.h>
#include <cstdint>

// Problem constants
#define BB   128
#define NN   196
#define DD   768
#define NTOK (BB * NN)      // 25088
#define EPSF 1e-6f
#define EMAX3 1024          // per-quadrant-CTA edge-list capacity

// ---------------- static device scratch (no allocations allowed) -------------
__device__ float    g_sim[(size_t)BB * NN * NN];   // fallback only (~19.7 MB)
__device__ float    g_w[NTOK];
__device__ int      g_members[NTOK];
__device__ int      g_goff[BB * (NN + 1)];
__device__ int      g_edge_cnt[BB * 3];
__device__ int      g_edges[BB * 3 * EMAX3];

// ---------------- kernel 1: cosine similarity via fp16 mma.sync --------------
// 3 CTAs per batch: (0,0) diag, (0,1) offdiag (+mirror via smem transpose),
// (1,1) diag. 8 warps (2x4), warp tile 64x32, mma.m16n8k16.f16 (fp32 acc).
// K-chunk 16, reg-prefetch + double-buffered smem (half2, 48B/row stride =
// conflict-free), ONE barrier per chunk. One thread owns one (matrix,row):
// fills, converts fp32->fp16, accumulates sum-of-squares. Norms applied at
// epilogue (fp16 mantissa == tf32 mantissa -> same accuracy, 2x throughput).
#define KC   16
#define NCH  (DD / KC)     // 48
#define RSTR 12            // row stride in uints (8 data half2 + 4 pad)

__device__ __forceinline__ void mma_f16(float (&d)[4], const unsigned (&a)[4],
                                        const unsigned (&b)[2]) {
    asm volatile("mma.sync.aligned.m16n8k16.row.col.f32.f16.f16.f32 "
                 "{%0,%1,%2,%3}, {%4,%5,%6,%7}, {%8,%9}, {%0,%1,%2,%3};\n"
                 : "+f"(d[0]), "+f"(d[1]), "+f"(d[2]), "+f"(d[3])
                 : "r"(a[0]), "r"(a[1]), "r"(a[2]), "r"(a[3]),
                   "r"(b[0]), "r"(b[1]));
}
__device__ __forceinline__ unsigned pack_h2(float x, float y) {
    __half2 h = __floats2half2_rn(x, y);
    return *reinterpret_cast<unsigned*>(&h);
}
__device__ __forceinline__ void rec_edge(int slot_base, int i, int j) {
    int slot = atomicAdd(&g_edge_cnt[slot_base], 1);
    if (slot < EMAX3) g_edges[slot_base * EMAX3 + slot] = (i << 8) | j;
}

__global__ void __launch_bounds__(256)
sim_kernel(const float* __restrict__ tok, float* __restrict__ sim_out_arg) {
    __shared__ float rnA[128], rnB[128];
    // [A buf0 | A buf1 | B buf0 | B buf1], each 128*RSTR uints (6144B)
    __shared__ __align__(16) unsigned sm_u[4 * 128 * RSTR];

    float* sim_out = sim_out_arg ? sim_out_arg : g_sim;
    int b  = blockIdx.y;
    int bx = blockIdx.x;                 // 0:(0,0)  1:(0,1)+mirror  2:(1,1)
    int ti = (bx == 2) ? 1 : 0;
    int tj = (bx >= 1) ? 1 : 0;
    int i0 = ti * 128, j0 = tj * 128;
    bool diag   = (ti == tj);
    bool mirror = (bx == 1);
    int tid  = threadIdx.x;
    int lane = tid & 31, warp = tid >> 5;
    int wm = warp >> 2, wn = warp & 3;
    int g4 = lane >> 2, t4 = lane & 3;
    int eslot = b * 3 + bx;

    if (tid == 0) g_edge_cnt[eslot] = 0;   // own counter; epilogue barriers order it

    float acc[4][4][4];
    #pragma unroll
    for (int ma = 0; ma < 4; ma++)
        #pragma unroll
        for (int na = 0; na < 4; na++)
            #pragma unroll
            for (int q = 0; q < 4; q++) acc[ma][na][q] = 0.f;

    const float* tokb = tok + (size_t)b * NN * DD;

    // ---- fill ownership: one thread = one (matrix,row) ----
    int mat  = tid >> 7;                 // 0 = A, 1 = B
    int frow = tid & 127;
    bool factive = (mat == 0) || (!diag);
    int grow = (mat == 0 ? i0 : j0) + frow;
    bool inb = factive && (grow < NN);
    const float4* src = (const float4*)(tokb + (size_t)(inb ? grow : 0) * DD);

    float ss = 0.f;
    float4 p[4];
    #pragma unroll
    for (int q = 0; q < 4; q++)
        p[q] = inb ? src[q] : make_float4(0.f, 0.f, 0.f, 0.f);

    unsigned* const Abase = sm_u;
    unsigned* const Bbase = sm_u + 2 * 128 * RSTR;

    for (int c = 0; c < NCH; c++) {
        unsigned* Au = Abase + (c & 1) * 128 * RSTR;
        unsigned* Bu = diag ? Au : (Bbase + (c & 1) * 128 * RSTR);

        if (factive) {
            unsigned* dst = (mat == 0 ? Au : (Bbase + (c & 1) * 128 * RSTR)) + frow * RSTR;
            #pragma unroll
            for (int q = 0; q < 4; q++)
                ss += p[q].x * p[q].x + p[q].y * p[q].y + p[q].z * p[q].z + p[q].w * p[q].w;
            uint4 s0 = make_uint4(pack_h2(p[0].x, p[0].y), pack_h2(p[0].z, p[0].w),
                                  pack_h2(p[1].x, p[1].y), pack_h2(p[1].z, p[1].w));
            uint4 s1 = make_uint4(pack_h2(p[2].x, p[2].y), pack_h2(p[2].z, p[2].w),
                                  pack_h2(p[3].x, p[3].y), pack_h2(p[3].z, p[3].w));
            *(uint4*)&dst[0] = s0;
            *(uint4*)&dst[4] = s1;
        }
        __syncthreads();

        // prefetch next chunk (overlaps with MMA below)
        if (c + 1 < NCH && inb) {
            const float4* s4 = src + (c + 1) * 4;
            #pragma unroll
            for (int q = 0; q < 4; q++) p[q] = s4[q];
        }

        // ---- MMA: one k16 step covers the chunk ----
        unsigned afr[4][4];
        #pragma unroll
        for (int ma = 0; ma < 4; ma++) {
            int r = wm * 64 + ma * 16 + g4;
            afr[ma][0] = Au[r * RSTR + t4];
            afr[ma][1] = Au[(r + 8) * RSTR + t4];
            afr[ma][2] = Au[r * RSTR + 4 + t4];
            afr[ma][3] = Au[(r + 8) * RSTR + 4 + t4];
        }
        unsigned bfr[4][2];
        #pragma unroll
        for (int na = 0; na < 4; na++) {
            int cidx = wn * 32 + na * 8 + g4;
            bfr[na][0] = Bu[cidx * RSTR + t4];
            bfr[na][1] = Bu[cidx * RSTR + 4 + t4];
        }
        #pragma unroll
        for (int ma = 0; ma < 4; ma++)
            #pragma unroll
            for (int na = 0; na < 4; na++)
                mma_f16(acc[ma][na], afr[ma], bfr[na]);
        // no trailing barrier: next fill writes the OTHER buffer; the reuse
        // hazard (c+2 vs compute c) is fenced by the next iteration's barrier.
    }

    // ---- per-row reciprocal norms (each thread owns its row) ----
    if (factive) {
        float rn = 1.0f / fmaxf(sqrtf(ss), 1e-12f);
        if (mat == 0) rnA[frow] = rn;
        else          rnB[frow] = rn;
    }
    __syncthreads();
    const float* rnBp = diag ? rnA : rnB;

    // ---- epilogue 1: this quadrant's tile (coalesced float2, scaled) ----
    #pragma unroll
    for (int ma = 0; ma < 4; ma++) {
        #pragma unroll
        for (int na = 0; na < 4; na++) {
            int lj = wn * 32 + na * 8 + 2 * t4;
            int gj = j0 + lj;
            if (gj >= NN) continue;
            float rb0 = rnBp[lj], rb1 = rnBp[lj + 1];
            #pragma unroll
            for (int h = 0; h < 2; h++) {
                int li = wm * 64 + ma * 16 + g4 + h * 8;
                int gi = i0 + li;
                if (gi >= NN) continue;
                float ra = rnA[li];
                float v0 = acc[ma][na][h * 2 + 0] * ra * rb0;
                float v1 = acc[ma][na][h * 2 + 1] * ra * rb1;
                if (diag) {
                    if (gi == gj)     v0 = 0.f;
                    if (gi == gj + 1) v1 = 0.f;
                }
                if (v0 > 0.9f) rec_edge(eslot, gi, gj);
                if (v1 > 0.9f && gj + 1 < NN) rec_edge(eslot, gi, gj + 1);
                *(float2*)&sim_out[((size_t)b * NN + gi) * NN + gj] = make_float2(v0, v1);
            }
        }
    }

    // ---- epilogue 2: mirror (1,0) via smem transpose (off-diag CTA only) ----
    if (mirror) {
        float* S = (float*)sm_u;         // 32 x 132 staging (16.9KB <= 24KB)
        #pragma unroll
        for (int cb = 0; cb < 3; cb++) {   // local col chunks; cb=3 all OOB
            __syncthreads();
            if (wn == cb) {
                #pragma unroll
                for (int ma = 0; ma < 4; ma++)
                    #pragma unroll
                    for (int na = 0; na < 4; na++)
                        #pragma unroll
                        for (int q = 0; q < 4; q++) {
                            int jc = na * 8 + 2 * t4 + (q & 1);
                            int il = wm * 64 + ma * 16 + g4 + 8 * (q >> 1);
                            S[jc * 132 + il] = acc[ma][na][q] * rnA[il] * rnBp[cb * 32 + jc];
                        }
            }
            __syncthreads();
            #pragma unroll
            for (int it = 0; it < 4; it++) {
                int jc = it * 8 + (tid >> 5);
                int gj = 128 + cb * 32 + jc;       // mirror row
                if (gj >= NN) continue;
                int i = (tid & 31) * 4;
                float4 v = *(float4*)&S[jc * 132 + i];
                if (v.x > 0.9f) rec_edge(eslot, gj, i + 0);
                if (v.y > 0.9f) rec_edge(eslot, gj, i + 1);
                if (v.z > 0.9f) rec_edge(eslot, gj, i + 2);
                if (v.w > 0.9f) rec_edge(eslot, gj, i + 3);
                *(float4*)&sim_out[((size_t)b * NN + gj) * NN + i] = v;
            }
        }
    }
}

// ---------------- kernel 2: grouping (fused gmax + importance) ---------------
__global__ void __launch_bounds__(256, 1)
group_kernel(const float* __restrict__ m, const float* __restrict__ s,
             const float* __restrict__ sim_in_arg,
             float* out_imp, float* out_gids) {
    int b = blockIdx.x, tid = threadIdx.x;
    const float* sim_in = sim_in_arg ? sim_in_arg : g_sim;
    __shared__ unsigned adj[NN][8];
    __shared__ float simp[NN];
    __shared__ int   sgid[NN];
    __shared__ float denom[NN];
    __shared__ int   cnt[NN];
    __shared__ int   off[NN + 1];
    __shared__ int   cur[NN];
    __shared__ float lo[256], hi[256];
    __shared__ float wr0[8], wr1[8];
    __shared__ unsigned assigned[8], reach[8], nxt[8];
    __shared__ int s_changed, s_ng, s_any;

    // ---- global max of motion / saliency (deterministic per-CTA scan) ----
    float mx0 = 0.f, mx1 = 0.f;
    for (int i = tid; i < NTOK; i += 256) {
        mx0 = fmaxf(mx0, m[i]);
        mx1 = fmaxf(mx1, s[i]);
    }
    #pragma unroll
    for (int o = 16; o; o >>= 1) {
        mx0 = fmaxf(mx0, __shfl_xor_sync(0xffffffffu, mx0, o));
        mx1 = fmaxf(mx1, __shfl_xor_sync(0xffffffffu, mx1, o));
    }
    int lane = tid & 31, warp = tid >> 5;
    if (lane == 0) { wr0[warp] = mx0; wr1[warp] = mx1; }
    __syncthreads();
    float gm0 = wr0[0], gm1 = wr1[0];
    #pragma unroll
    for (int w = 1; w < 8; w++) { gm0 = fmaxf(gm0, wr0[w]); gm1 = fmaxf(gm1, wr1[w]); }

    // ---- importance for this batch ----
    bool valid = (tid < NN);
    float v = 0.f;
    if (valid) {
        float mn = m[b * NN + tid] / (gm0 + EPSF);
        float sn = s[b * NN + tid] / (gm1 + EPSF);
        v = 0.5f * mn + 0.5f * sn;
    }
    lo[tid] = valid ? v :  CUDART_INF_F;
    hi[tid] = valid ? v : -CUDART_INF_F;
    __syncthreads();
    for (int o = 128; o; o >>= 1) {
        if (tid < o) { lo[tid] = fminf(lo[tid], lo[tid + o]); hi[tid] = fmaxf(hi[tid], hi[tid + o]); }
        __syncthreads();
    }
    float l = lo[0], h = hi[0];
    if (valid) {
        float r = (v - l) / (h - l + EPSF);
        simp[tid] = r;
        if (out_imp) out_imp[b * NN + tid] = r;
    }
    for (int i = tid; i < NN; i += 256) { cnt[i] = 0; denom[i] = EPSF; }
    if (tid < 8) assigned[tid] = 0u;
    if (tid == 0) { s_ng = 0; s_any = 0; }
    __syncthreads();

    // ---- adjacency from per-quadrant edge lists ----
    int e0 = g_edge_cnt[b * 3 + 0];
    int e1 = g_edge_cnt[b * 3 + 1];
    int e2 = g_edge_cnt[b * 3 + 2];
    int etot = e0 + e1 + e2;
    bool overflow = (e0 > EMAX3) || (e1 > EMAX3) || (e2 > EMAX3);

    if (etot == 0) {
        for (int i = tid; i < NN; i += 256) sgid[i] = i;
        if (tid == 0) s_ng = NN;
        __syncthreads();
    } else {
        for (int i = tid; i < NN * 8; i += 256) (&adj[0][0])[i] = 0u;
        __syncthreads();
        if (!overflow) {
            #pragma unroll
            for (int q = 0; q < 3; q++) {
                int ec = (q == 0) ? e0 : (q == 1) ? e1 : e2;
                const int* el = &g_edges[(b * 3 + q) * EMAX3];
                for (int e = tid; e < ec; e += 256) {
                    int pk = el[e];
                    int i = pk >> 8, j = pk & 255;
                    if (j < NN && (1.0f - simp[i]) > 0.5f) {
                        atomicOr(&adj[i][j >> 5], 1u << (j & 31));
                        s_any = 1;
                    }
                }
            }
        } else {
            const float* simb = sim_in + (size_t)b * NN * NN;
            for (int idx = tid; idx < NN * NN; idx += 256) {
                int i = idx / NN, j = idx - i * NN;
                float sv = simb[idx];
                if (sv > 0.9f && (1.0f - simp[i]) > 0.5f) {
                    atomicOr(&adj[i][j >> 5], 1u << (j & 31));
                    s_any = 1;
                }
            }
        }
        __syncthreads();

        if (s_any == 0) {
            for (int i = tid; i < NN; i += 256) sgid[i] = i;
            if (tid == 0) s_ng = NN;
            __syncthreads();
        } else {
            for (int r = 0; r < NN; r++) {
                if ((assigned[r >> 5] >> (r & 31)) & 1u) continue;
                if (tid < 8) reach[tid] = (tid == (r >> 5)) ? (1u << (r & 31)) : 0u;
                __syncthreads();
                while (true) {
                    if (tid < 8) nxt[tid] = 0u;
                    if (tid == 0) s_changed = 0;
                    __syncthreads();
                    for (int i = tid; i < NN; i += 256) {
                        if ((reach[i >> 5] >> (i & 31)) & 1u) {
                            #pragma unroll
                            for (int w = 0; w < 7; w++) {
                                unsigned vv = adj[i][w];
                                if (vv) atomicOr(&nxt[w], vv);
                            }
                        }
                    }
                    __syncthreads();
                    if (tid < 8) {
                        unsigned nv = reach[tid] | (nxt[tid] & ~assigned[tid]);
                        if (nv != reach[tid]) s_changed = 1;
                        nxt[tid] = nv;
                    }
                    __syncthreads();
                    if (tid < 8) reach[tid] = nxt[tid];
                    __syncthreads();
                    if (!s_changed) break;
                }
                int gid = s_ng;
                for (int i = tid; i < NN; i += 256)
                    if ((reach[i >> 5] >> (i & 31)) & 1u) sgid[i] = gid;
                if (tid < 8) assigned[tid] |= reach[tid];
                __syncthreads();
                if (tid == 0) s_ng = gid + 1;
                __syncthreads();
            }
        }
    }

    // ---- weights + CSR ----
    for (int i = tid; i < NN; i += 256) atomicAdd(&denom[sgid[i]], simp[i]);
    __syncthreads();
    for (int i = tid; i < NN; i += 256) {
        g_w[b * NN + i] = simp[i] / denom[sgid[i]];
        if (out_gids) out_gids[b * NN + i] = (float)sgid[i];
        atomicAdd(&cnt[sgid[i]], 1);
    }
    __syncthreads();
    if (tid == 0) {
        off[0] = 0;
        for (int g = 0; g < NN; g++) off[g + 1] = off[g] + cnt[g];
    }
    __syncthreads();
    for (int g = tid; g < NN; g += 256) cur[g] = off[g];
    for (int g = tid; g < NN + 1; g += 256) g_goff[b * (NN + 1) + g] = off[g];
    __syncthreads();
    for (int i = tid; i < NN; i += 256) {
        int g = sgid[i];
        int pos = atomicAdd(&cur[g], 1);
        g_members[b * NN + pos] = i;
    }
}

// ---------------- kernel 3: merged tokens (CSR gather, float4) ----------------
__global__ void __launch_bounds__(192)
merge_kernel(const float* __restrict__ tok, float* __restrict__ out) {
    int b = blockIdx.y, g = blockIdx.x, tid = threadIdx.x;
    int o0 = g_goff[b * (NN + 1) + g];
    int o1 = g_goff[b * (NN + 1) + g + 1];
    float4 a = make_float4(0.f, 0.f, 0.f, 0.f);
    const float4* tokb = (const float4*)(tok + (size_t)b * NN * DD);
    for (int k = o0; k < o1; k++) {
        int i = g_members[b * NN + k];
        float wv = g_w[b * NN + i];
        float4 v = tokb[(size_t)i * (DD / 4) + tid];
        a.x += v.x * wv; a.y += v.y * wv; a.z += v.z * wv; a.w += v.w * wv;
    }
    ((float4*)out)[((size_t)b * NN + g) * (DD / 4) + tid] = a;
}

// ---------------- launch ------------------------------------------------------
extern "C" void kernel_launch(void* const* d_in, const int* in_sizes, int n_in,
                              void* d_out, int out_size) {
    const float* tokens = (const float*)d_in[0];
    const float* motion = (const float*)d_in[1];
    const float* sal    = (const float*)d_in[2];
    float* out = (float*)d_out;

    const long long SZ_M = (long long)BB * NN * DD;   // 19267584
    const long long SZ_S = (long long)BB * NN * NN;   //  4917248
    const long long SZ_I = (long long)BB * NN;        //    25088
    long long osz = (long long)out_size;

    float* out_sim  = (osz >= SZ_M + SZ_S)            ? out + SZ_M               : nullptr;
    float* out_imp  = (osz >= SZ_M + SZ_S + SZ_I)     ? out + SZ_M + SZ_S        : nullptr;
    float* out_gids = (osz >= SZ_M + SZ_S + 2 * SZ_I) ? out + SZ_M + SZ_S + SZ_I : nullptr;

    sim_kernel<<<dim3(3, BB), 256>>>(tokens, out_sim);
    group_kernel<<<BB, 256>>>(motion, sal, out_sim, out_imp, out_gids);
    merge_kernel<<<dim3(NN, BB), 192>>>(tokens, out);
}

// round 13
// speedup vs baseline: 1.0004x; 1.0004x over previous
#include <cuda_runtime.h>
#include <cuda_bf16.h>
#include <cuda_fp16.h>
#include <math_constants.h>
#include <cstdint>

// Problem constants
#define BB   128
#define NN   196
#define DD   768
#define NTOK (BB * NN)      // 25088
#define EPSF 1e-6f
#define EMAX3 1024          // per-quadrant-CTA edge-list capacity

// ---------------- static device scratch (no allocations allowed) -------------
__device__ float    g_sim[(size_t)BB * NN * NN];   // fallback only (~19.7 MB)
__device__ float    g_w[NTOK];
__device__ int      g_members[NTOK];
__device__ int      g_goff[BB * (NN + 1)];
__device__ int      g_edge_cnt[BB * 3];
__device__ int      g_edges[BB * 3 * EMAX3];

// ---------------- kernel 1: cosine similarity via fp16 mma.sync --------------
// 3 CTAs per batch: (0,0) diag, (0,1) offdiag (+mirror via smem transpose),
// (1,1) diag. 8 warps (2x4), warp tile 64x32, mma.m16n8k16.f16 (fp32 acc).
// K-chunk 32 = TWO k16 steps per barrier (round-12 lesson: keep >=32 MMAs of
// work per sync). 24 barriers total. One thread owns one (matrix,row); fp32
// loads converted to half2 at prefetch (16 uint regs). Row norms from fill-
// time sum-of-squares, applied at epilogue. Edge detection fused.
#define KC   32
#define NCH  (DD / KC)     // 24
#define RSTR 20            // row stride in uints (16 data half2 + 4 pad)

__device__ __forceinline__ void mma_f16(float (&d)[4], const unsigned (&a)[4],
                                        const unsigned (&b)[2]) {
    asm volatile("mma.sync.aligned.m16n8k16.row.col.f32.f16.f16.f32 "
                 "{%0,%1,%2,%3}, {%4,%5,%6,%7}, {%8,%9}, {%0,%1,%2,%3};\n"
                 : "+f"(d[0]), "+f"(d[1]), "+f"(d[2]), "+f"(d[3])
                 : "r"(a[0]), "r"(a[1]), "r"(a[2]), "r"(a[3]),
                   "r"(b[0]), "r"(b[1]));
}
__device__ __forceinline__ unsigned pack_h2(float x, float y) {
    __half2 h = __floats2half2_rn(x, y);
    return *reinterpret_cast<unsigned*>(&h);
}
__device__ __forceinline__ void rec_edge(int slot_base, int i, int j) {
    int slot = atomicAdd(&g_edge_cnt[slot_base], 1);
    if (slot < EMAX3) g_edges[slot_base * EMAX3 + slot] = (i << 8) | j;
}

__global__ void __launch_bounds__(256, 2)
sim_kernel(const float* __restrict__ tok, float* __restrict__ sim_out_arg) {
    __shared__ float rnA[128], rnB[128];
    // [A buf0 | A buf1 | B buf0 | B buf1], each 128*RSTR uints (10240B)
    __shared__ __align__(16) unsigned sm_u[4 * 128 * RSTR];

    float* sim_out = sim_out_arg ? sim_out_arg : g_sim;
    int b  = blockIdx.y;
    int bx = blockIdx.x;                 // 0:(0,0)  1:(0,1)+mirror  2:(1,1)
    int ti = (bx == 2) ? 1 : 0;
    int tj = (bx >= 1) ? 1 : 0;
    int i0 = ti * 128, j0 = tj * 128;
    bool diag   = (ti == tj);
    bool mirror = (bx == 1);
    int tid  = threadIdx.x;
    int lane = tid & 31, warp = tid >> 5;
    int wm = warp >> 2, wn = warp & 3;
    int g4 = lane >> 2, t4 = lane & 3;
    int eslot = b * 3 + bx;

    if (tid == 0) g_edge_cnt[eslot] = 0;   // own counter; epilogue barriers order it

    float acc[4][4][4];
    #pragma unroll
    for (int ma = 0; ma < 4; ma++)
        #pragma unroll
        for (int na = 0; na < 4; na++)
            #pragma unroll
            for (int q = 0; q < 4; q++) acc[ma][na][q] = 0.f;

    const float* tokb = tok + (size_t)b * NN * DD;

    // ---- fill ownership: one thread = one (matrix,row) ----
    int mat  = tid >> 7;                 // 0 = A, 1 = B
    int frow = tid & 127;
    bool factive = (mat == 0) || (!diag);
    int grow = (mat == 0 ? i0 : j0) + frow;
    bool inb = factive && (grow < NN);
    const float4* src = (const float4*)(tokb + (size_t)(inb ? grow : 0) * DD);

    float ss = 0.f;
    unsigned h[16];
    #pragma unroll
    for (int q = 0; q < 16; q++) h[q] = 0u;

    // preload + convert chunk 0
    if (inb) {
        #pragma unroll
        for (int g = 0; g < 2; g++) {
            float4 v0 = src[g * 4 + 0], v1 = src[g * 4 + 1];
            float4 v2 = src[g * 4 + 2], v3 = src[g * 4 + 3];
            ss += v0.x * v0.x + v0.y * v0.y + v0.z * v0.z + v0.w * v0.w
                + v1.x * v1.x + v1.y * v1.y + v1.z * v1.z + v1.w * v1.w
                + v2.x * v2.x + v2.y * v2.y + v2.z * v2.z + v2.w * v2.w
                + v3.x * v3.x + v3.y * v3.y + v3.z * v3.z + v3.w * v3.w;
            h[g * 8 + 0] = pack_h2(v0.x, v0.y); h[g * 8 + 1] = pack_h2(v0.z, v0.w);
            h[g * 8 + 2] = pack_h2(v1.x, v1.y); h[g * 8 + 3] = pack_h2(v1.z, v1.w);
            h[g * 8 + 4] = pack_h2(v2.x, v2.y); h[g * 8 + 5] = pack_h2(v2.z, v2.w);
            h[g * 8 + 6] = pack_h2(v3.x, v3.y); h[g * 8 + 7] = pack_h2(v3.z, v3.w);
        }
    }

    unsigned* const Abase = sm_u;
    unsigned* const Bbase = sm_u + 2 * 128 * RSTR;

    for (int c = 0; c < NCH; c++) {
        unsigned* Au = Abase + (c & 1) * 128 * RSTR;
        unsigned* Bu = diag ? Au : (Bbase + (c & 1) * 128 * RSTR);

        // store converted chunk c (4x STS.128, conflict-free via RSTR=20)
        if (factive) {
            unsigned* dst = (mat == 0 ? Au : (Bbase + (c & 1) * 128 * RSTR)) + frow * RSTR;
            *(uint4*)&dst[0]  = make_uint4(h[0],  h[1],  h[2],  h[3]);
            *(uint4*)&dst[4]  = make_uint4(h[4],  h[5],  h[6],  h[7]);
            *(uint4*)&dst[8]  = make_uint4(h[8],  h[9],  h[10], h[11]);
            *(uint4*)&dst[12] = make_uint4(h[12], h[13], h[14], h[15]);
        }
        __syncthreads();

        // prefetch + convert chunk c+1 (overlaps with MMA below)
        if (c + 1 < NCH && inb) {
            const float4* s4 = src + (c + 1) * 8;
            #pragma unroll
            for (int g = 0; g < 2; g++) {
                float4 v0 = s4[g * 4 + 0], v1 = s4[g * 4 + 1];
                float4 v2 = s4[g * 4 + 2], v3 = s4[g * 4 + 3];
                ss += v0.x * v0.x + v0.y * v0.y + v0.z * v0.z + v0.w * v0.w
                    + v1.x * v1.x + v1.y * v1.y + v1.z * v1.z + v1.w * v1.w
                    + v2.x * v2.x + v2.y * v2.y + v2.z * v2.z + v2.w * v2.w
                    + v3.x * v3.x + v3.y * v3.y + v3.z * v3.z + v3.w * v3.w;
                h[g * 8 + 0] = pack_h2(v0.x, v0.y); h[g * 8 + 1] = pack_h2(v0.z, v0.w);
                h[g * 8 + 2] = pack_h2(v1.x, v1.y); h[g * 8 + 3] = pack_h2(v1.z, v1.w);
                h[g * 8 + 4] = pack_h2(v2.x, v2.y); h[g * 8 + 5] = pack_h2(v2.z, v2.w);
                h[g * 8 + 6] = pack_h2(v3.x, v3.y); h[g * 8 + 7] = pack_h2(v3.z, v3.w);
            }
        }

        // ---- MMA: two k16 steps cover the 32-wide chunk ----
        #pragma unroll
        for (int ks = 0; ks < 2; ks++) {
            int kb = ks * 8 + t4;
            unsigned afr[4][4];
            #pragma unroll
            for (int ma = 0; ma < 4; ma++) {
                int r = wm * 64 + ma * 16 + g4;
                afr[ma][0] = Au[r * RSTR + kb];
                afr[ma][1] = Au[(r + 8) * RSTR + kb];
                afr[ma][2] = Au[r * RSTR + 4 + kb];
                afr[ma][3] = Au[(r + 8) * RSTR + 4 + kb];
            }
            unsigned bfr[4][2];
            #pragma unroll
            for (int na = 0; na < 4; na++) {
                int cidx = wn * 32 + na * 8 + g4;
                bfr[na][0] = Bu[cidx * RSTR + kb];
                bfr[na][1] = Bu[cidx * RSTR + 4 + kb];
            }
            #pragma unroll
            for (int ma = 0; ma < 4; ma++)
                #pragma unroll
                for (int na = 0; na < 4; na++)
                    mma_f16(acc[ma][na], afr[ma], bfr[na]);
        }
        // no trailing barrier: store(c+2) is ordered after barrier(c+1), which
        // all warps reach only after finishing mma(c) -- hazard-free.
    }

    // ---- per-row reciprocal norms (each thread owns its row) ----
    if (factive) {
        float rn = 1.0f / fmaxf(sqrtf(ss), 1e-12f);
        if (mat == 0) rnA[frow] = rn;
        else          rnB[frow] = rn;
    }
    __syncthreads();
    const float* rnBp = diag ? rnA : rnB;

    // ---- epilogue 1: this quadrant's tile (coalesced float2, scaled) ----
    #pragma unroll
    for (int ma = 0; ma < 4; ma++) {
        #pragma unroll
        for (int na = 0; na < 4; na++) {
            int lj = wn * 32 + na * 8 + 2 * t4;
            int gj = j0 + lj;
            if (gj >= NN) continue;
            float rb0 = rnBp[lj], rb1 = rnBp[lj + 1];
            #pragma unroll
            for (int hh = 0; hh < 2; hh++) {
                int li = wm * 64 + ma * 16 + g4 + hh * 8;
                int gi = i0 + li;
                if (gi >= NN) continue;
                float ra = rnA[li];
                float v0 = acc[ma][na][hh * 2 + 0] * ra * rb0;
                float v1 = acc[ma][na][hh * 2 + 1] * ra * rb1;
                if (diag) {
                    if (gi == gj)     v0 = 0.f;
                    if (gi == gj + 1) v1 = 0.f;
                }
                if (v0 > 0.9f) rec_edge(eslot, gi, gj);
                if (v1 > 0.9f && gj + 1 < NN) rec_edge(eslot, gi, gj + 1);
                *(float2*)&sim_out[((size_t)b * NN + gi) * NN + gj] = make_float2(v0, v1);
            }
        }
    }

    // ---- epilogue 2: mirror (1,0) via smem transpose (off-diag CTA only) ----
    if (mirror) {
        float* S = (float*)sm_u;         // 32 x 132 staging (16.9KB <= 40KB)
        #pragma unroll
        for (int cb = 0; cb < 3; cb++) {   // local col chunks; cb=3 all OOB
            __syncthreads();
            if (wn == cb) {
                #pragma unroll
                for (int ma = 0; ma < 4; ma++)
                    #pragma unroll
                    for (int na = 0; na < 4; na++)
                        #pragma unroll
                        for (int q = 0; q < 4; q++) {
                            int jc = na * 8 + 2 * t4 + (q & 1);
                            int il = wm * 64 + ma * 16 + g4 + 8 * (q >> 1);
                            S[jc * 132 + il] = acc[ma][na][q] * rnA[il] * rnBp[cb * 32 + jc];
                        }
            }
            __syncthreads();
            #pragma unroll
            for (int it = 0; it < 4; it++) {
                int jc = it * 8 + (tid >> 5);
                int gj = 128 + cb * 32 + jc;       // mirror row
                if (gj >= NN) continue;
                int i = (tid & 31) * 4;
                float4 v = *(float4*)&S[jc * 132 + i];
                if (v.x > 0.9f) rec_edge(eslot, gj, i + 0);
                if (v.y > 0.9f) rec_edge(eslot, gj, i + 1);
                if (v.z > 0.9f) rec_edge(eslot, gj, i + 2);
                if (v.w > 0.9f) rec_edge(eslot, gj, i + 3);
                *(float4*)&sim_out[((size_t)b * NN + gj) * NN + i] = v;
            }
        }
    }
}

// ---------------- kernel 2: grouping (fused gmax + importance) ---------------
__global__ void __launch_bounds__(256, 1)
group_kernel(const float* __restrict__ m, const float* __restrict__ s,
             const float* __restrict__ sim_in_arg,
             float* out_imp, float* out_gids) {
    int b = blockIdx.x, tid = threadIdx.x;
    const float* sim_in = sim_in_arg ? sim_in_arg : g_sim;
    __shared__ unsigned adj[NN][8];
    __shared__ float simp[NN];
    __shared__ int   sgid[NN];
    __shared__ float denom[NN];
    __shared__ int   cnt[NN];
    __shared__ int   off[NN + 1];
    __shared__ int   cur[NN];
    __shared__ float lo[256], hi[256];
    __shared__ float wr0[8], wr1[8];
    __shared__ unsigned assigned[8], reach[8], nxt[8];
    __shared__ int s_changed, s_ng, s_any;

    // ---- global max of motion / saliency (deterministic per-CTA scan) ----
    float mx0 = 0.f, mx1 = 0.f;
    for (int i = tid; i < NTOK; i += 256) {
        mx0 = fmaxf(mx0, m[i]);
        mx1 = fmaxf(mx1, s[i]);
    }
    #pragma unroll
    for (int o = 16; o; o >>= 1) {
        mx0 = fmaxf(mx0, __shfl_xor_sync(0xffffffffu, mx0, o));
        mx1 = fmaxf(mx1, __shfl_xor_sync(0xffffffffu, mx1, o));
    }
    int lane = tid & 31, warp = tid >> 5;
    if (lane == 0) { wr0[warp] = mx0; wr1[warp] = mx1; }
    __syncthreads();
    float gm0 = wr0[0], gm1 = wr1[0];
    #pragma unroll
    for (int w = 1; w < 8; w++) { gm0 = fmaxf(gm0, wr0[w]); gm1 = fmaxf(gm1, wr1[w]); }

    // ---- importance for this batch ----
    bool valid = (tid < NN);
    float v = 0.f;
    if (valid) {
        float mn = m[b * NN + tid] / (gm0 + EPSF);
        float sn = s[b * NN + tid] / (gm1 + EPSF);
        v = 0.5f * mn + 0.5f * sn;
    }
    lo[tid] = valid ? v :  CUDART_INF_F;
    hi[tid] = valid ? v : -CUDART_INF_F;
    __syncthreads();
    for (int o = 128; o; o >>= 1) {
        if (tid < o) { lo[tid] = fminf(lo[tid], lo[tid + o]); hi[tid] = fmaxf(hi[tid], hi[tid + o]); }
        __syncthreads();
    }
    float l = lo[0], h = hi[0];
    if (valid) {
        float r = (v - l) / (h - l + EPSF);
        simp[tid] = r;
        if (out_imp) out_imp[b * NN + tid] = r;
    }
    for (int i = tid; i < NN; i += 256) { cnt[i] = 0; denom[i] = EPSF; }
    if (tid < 8) assigned[tid] = 0u;
    if (tid == 0) { s_ng = 0; s_any = 0; }
    __syncthreads();

    // ---- adjacency from per-quadrant edge lists ----
    int e0 = g_edge_cnt[b * 3 + 0];
    int e1 = g_edge_cnt[b * 3 + 1];
    int e2 = g_edge_cnt[b * 3 + 2];
    int etot = e0 + e1 + e2;
    bool overflow = (e0 > EMAX3) || (e1 > EMAX3) || (e2 > EMAX3);

    if (etot == 0) {
        for (int i = tid; i < NN; i += 256) sgid[i] = i;
        if (tid == 0) s_ng = NN;
        __syncthreads();
    } else {
        for (int i = tid; i < NN * 8; i += 256) (&adj[0][0])[i] = 0u;
        __syncthreads();
        if (!overflow) {
            #pragma unroll
            for (int q = 0; q < 3; q++) {
                int ec = (q == 0) ? e0 : (q == 1) ? e1 : e2;
                const int* el = &g_edges[(b * 3 + q) * EMAX3];
                for (int e = tid; e < ec; e += 256) {
                    int pk = el[e];
                    int i = pk >> 8, j = pk & 255;
                    if (j < NN && (1.0f - simp[i]) > 0.5f) {
                        atomicOr(&adj[i][j >> 5], 1u << (j & 31));
                        s_any = 1;
                    }
                }
            }
        } else {
            const float* simb = sim_in + (size_t)b * NN * NN;
            for (int idx = tid; idx < NN * NN; idx += 256) {
                int i = idx / NN, j = idx - i * NN;
                float sv = simb[idx];
                if (sv > 0.9f && (1.0f - simp[i]) > 0.5f) {
                    atomicOr(&adj[i][j >> 5], 1u << (j & 31));
                    s_any = 1;
                }
            }
        }
        __syncthreads();

        if (s_any == 0) {
            for (int i = tid; i < NN; i += 256) sgid[i] = i;
            if (tid == 0) s_ng = NN;
            __syncthreads();
        } else {
            for (int r = 0; r < NN; r++) {
                if ((assigned[r >> 5] >> (r & 31)) & 1u) continue;
                if (tid < 8) reach[tid] = (tid == (r >> 5)) ? (1u << (r & 31)) : 0u;
                __syncthreads();
                while (true) {
                    if (tid < 8) nxt[tid] = 0u;
                    if (tid == 0) s_changed = 0;
                    __syncthreads();
                    for (int i = tid; i < NN; i += 256) {
                        if ((reach[i >> 5] >> (i & 31)) & 1u) {
                            #pragma unroll
                            for (int w = 0; w < 7; w++) {
                                unsigned vv = adj[i][w];
                                if (vv) atomicOr(&nxt[w], vv);
                            }
                        }
                    }
                    __syncthreads();
                    if (tid < 8) {
                        unsigned nv = reach[tid] | (nxt[tid] & ~assigned[tid]);
                        if (nv != reach[tid]) s_changed = 1;
                        nxt[tid] = nv;
                    }
                    __syncthreads();
                    if (tid < 8) reach[tid] = nxt[tid];
                    __syncthreads();
                    if (!s_changed) break;
                }
                int gid = s_ng;
                for (int i = tid; i < NN; i += 256)
                    if ((reach[i >> 5] >> (i & 31)) & 1u) sgid[i] = gid;
                if (tid < 8) assigned[tid] |= reach[tid];
                __syncthreads();
                if (tid == 0) s_ng = gid + 1;
                __syncthreads();
            }
        }
    }

    // ---- weights + CSR ----
    for (int i = tid; i < NN; i += 256) atomicAdd(&denom[sgid[i]], simp[i]);
    __syncthreads();
    for (int i = tid; i < NN; i += 256) {
        g_w[b * NN + i] = simp[i] / denom[sgid[i]];
        if (out_gids) out_gids[b * NN + i] = (float)sgid[i];
        atomicAdd(&cnt[sgid[i]], 1);
    }
    __syncthreads();
    if (tid == 0) {
        off[0] = 0;
        for (int g = 0; g < NN; g++) off[g + 1] = off[g] + cnt[g];
    }
    __syncthreads();
    for (int g = tid; g < NN; g += 256) cur[g] = off[g];
    for (int g = tid; g < NN + 1; g += 256) g_goff[b * (NN + 1) + g] = off[g];
    __syncthreads();
    for (int i = tid; i < NN; i += 256) {
        int g = sgid[i];
        int pos = atomicAdd(&cur[g], 1);
        g_members[b * NN + pos] = i;
    }
}

// ---------------- kernel 3: merged tokens (CSR gather, float4) ----------------
__global__ void __launch_bounds__(192)
merge_kernel(const float* __restrict__ tok, float* __restrict__ out) {
    int b = blockIdx.y, g = blockIdx.x, tid = threadIdx.x;
    int o0 = g_goff[b * (NN + 1) + g];
    int o1 = g_goff[b * (NN + 1) + g + 1];
    float4 a = make_float4(0.f, 0.f, 0.f, 0.f);
    const float4* tokb = (const float4*)(tok + (size_t)b * NN * DD);
    for (int k = o0; k < o1; k++) {
        int i = g_members[b * NN + k];
        float wv = g_w[b * NN + i];
        float4 v = tokb[(size_t)i * (DD / 4) + tid];
        a.x += v.x * wv; a.y += v.y * wv; a.z += v.z * wv; a.w += v.w * wv;
    }
    ((float4*)out)[((size_t)b * NN + g) * (DD / 4) + tid] = a;
}

// ---------------- launch ------------------------------------------------------
extern "C" void kernel_launch(void* const* d_in, const int* in_sizes, int n_in,
                              void* d_out, int out_size) {
    const float* tokens = (const float*)d_in[0];
    const float* motion = (const float*)d_in[1];
    const float* sal    = (const float*)d_in[2];
    float* out = (float*)d_out;

    const long long SZ_M = (long long)BB * NN * DD;   // 19267584
    const long long SZ_S = (long long)BB * NN * NN;   //  4917248
    const long long SZ_I = (long long)BB * NN;        //    25088
    long long osz = (long long)out_size;

    float* out_sim  = (osz >= SZ_M + SZ_S)            ? out + SZ_M               : nullptr;
    float* out_imp  = (osz >= SZ_M + SZ_S + SZ_I)     ? out + SZ_M + SZ_S        : nullptr;
    float* out_gids = (osz >= SZ_M + SZ_S + 2 * SZ_I) ? out + SZ_M + SZ_S + SZ_I : nullptr;

    sim_kernel<<<dim3(3, BB), 256>>>(tokens, out_sim);
    group_kernel<<<BB, 256>>>(motion, sal, out_sim, out_imp, out_gids);
    merge_kernel<<<dim3(NN, BB), 192>>>(tokens, out);
}

// round 15
// speedup vs baseline: 1.0543x; 1.0539x over previous
#include <cuda_runtime.h>
#include <cuda_bf16.h>
#include <cuda_fp16.h>
#include <math_constants.h>
#include <cstdint>

// Problem constants
#define BB   128
#define NN   196
#define DD   768
#define NTOK (BB * NN)      // 25088
#define EPSF 1e-6f
#define EMAX3 1024          // per-quadrant-CTA edge-list capacity

// ---------------- static device scratch (no allocations allowed) -------------
__device__ float    g_sim[(size_t)BB * NN * NN];   // fallback only (~19.7 MB)
__device__ float    g_w[NTOK];
__device__ int      g_members[NTOK];
__device__ int      g_goff[BB * (NN + 1)];
__device__ int      g_edge_cnt[BB * 3];
__device__ int      g_edges[BB * 3 * EMAX3];

// ---------------- kernel 1: cosine similarity via fp16 mma.sync --------------
// 3 CTAs per batch: (0,0) diag, (0,1) offdiag (+mirror via smem transpose),
// (1,1) diag. 8 warps (2x4), warp tile 64x32, mma.m16n8k16.f16 (fp32 acc).
// K-chunk 32 = two k16 steps (32 HMMA per barrier, 24 barriers). COALESCED
// fill (round-13 lesson: one-thread-one-row gathers killed the feed): 4
// threads per row, each owning 2 consecutive float4 (32B contiguous), packed
// to half2 in regs, one STS.128 per row-iter. RSTR=20 keeps all fragment
// LDS.32 conflict-free. Row norms from fill-time sum of squares (4-lane
// shuffle reduce). Edge detection fused; per-quadrant-CTA edge lists.
#define KC   32
#define NCH  (DD / KC)     // 24
#define RSTR 20            // row stride in uints (16 data half2 + 4 pad)

__device__ __forceinline__ void mma_f16(float (&d)[4], const unsigned (&a)[4],
                                        const unsigned (&b)[2]) {
    asm volatile("mma.sync.aligned.m16n8k16.row.col.f32.f16.f16.f32 "
                 "{%0,%1,%2,%3}, {%4,%5,%6,%7}, {%8,%9}, {%0,%1,%2,%3};\n"
                 : "+f"(d[0]), "+f"(d[1]), "+f"(d[2]), "+f"(d[3])
                 : "r"(a[0]), "r"(a[1]), "r"(a[2]), "r"(a[3]),
                   "r"(b[0]), "r"(b[1]));
}
__device__ __forceinline__ unsigned pack_h2(float x, float y) {
    __half2 h = __floats2half2_rn(x, y);
    return *reinterpret_cast<unsigned*>(&h);
}
__device__ __forceinline__ void rec_edge(int slot_base, int i, int j) {
    int slot = atomicAdd(&g_edge_cnt[slot_base], 1);
    if (slot < EMAX3) g_edges[slot_base * EMAX3 + slot] = (i << 8) | j;
}

__global__ void __launch_bounds__(256, 2)
sim_kernel(const float* __restrict__ tok, float* __restrict__ sim_out_arg) {
    __shared__ float rnA[128], rnB[128];
    // [A buf0 | A buf1 | B buf0 | B buf1], each 128*RSTR uints (10240B)
    __shared__ __align__(16) unsigned sm_u[4 * 128 * RSTR];

    float* sim_out = sim_out_arg ? sim_out_arg : g_sim;
    int b  = blockIdx.y;
    int bx = blockIdx.x;                 // 0:(0,0)  1:(0,1)+mirror  2:(1,1)
    int ti = (bx == 2) ? 1 : 0;
    int tj = (bx >= 1) ? 1 : 0;
    int i0 = ti * 128, j0 = tj * 128;
    bool diag   = (ti == tj);
    bool mirror = (bx == 1);
    int tid  = threadIdx.x;
    int lane = tid & 31, warp = tid >> 5;
    int wm = warp >> 2, wn = warp & 3;
    int g4 = lane >> 2, t4 = lane & 3;
    int eslot = b * 3 + bx;

    if (tid == 0) g_edge_cnt[eslot] = 0;   // own counter; epilogue barriers order it

    float acc[4][4][4];
    #pragma unroll
    for (int ma = 0; ma < 4; ma++)
        #pragma unroll
        for (int na = 0; na < 4; na++)
            #pragma unroll
            for (int q = 0; q < 4; q++) acc[ma][na][q] = 0.f;

    const float* tokb = tok + (size_t)b * NN * DD;

    // ---- coalesced fill ownership: 4 threads per row, 2 row-iters ----
    int frow0 = tid >> 2;                // 0..63
    int ft4   = tid & 3;                 // float4-pair slot within row
    const float4* srcA[2];
    const float4* srcB[2];
    bool inbA[2], inbB[2];
    #pragma unroll
    for (int it = 0; it < 2; it++) {
        int ra = i0 + it * 64 + frow0;
        int rb = j0 + it * 64 + frow0;
        inbA[it] = (ra < NN);
        inbB[it] = (!diag) && (rb < NN);
        srcA[it] = (const float4*)(tokb + (size_t)(inbA[it] ? ra : 0) * DD);
        srcB[it] = (const float4*)(tokb + (size_t)(inbB[it] ? rb : 0) * DD);
    }

    float ssa[2] = {0.f, 0.f}, ssb[2] = {0.f, 0.f};
    unsigned hA[8], hB[8];
    #pragma unroll
    for (int q = 0; q < 8; q++) { hA[q] = 0u; hB[q] = 0u; }

    // preload + convert chunk 0
    #pragma unroll
    for (int it = 0; it < 2; it++) {
        if (inbA[it]) {
            float4 v0 = srcA[it][ft4 * 2], v1 = srcA[it][ft4 * 2 + 1];
            ssa[it] += v0.x * v0.x + v0.y * v0.y + v0.z * v0.z + v0.w * v0.w
                     + v1.x * v1.x + v1.y * v1.y + v1.z * v1.z + v1.w * v1.w;
            hA[it * 4 + 0] = pack_h2(v0.x, v0.y); hA[it * 4 + 1] = pack_h2(v0.z, v0.w);
            hA[it * 4 + 2] = pack_h2(v1.x, v1.y); hA[it * 4 + 3] = pack_h2(v1.z, v1.w);
        }
        if (inbB[it]) {
            float4 v0 = srcB[it][ft4 * 2], v1 = srcB[it][ft4 * 2 + 1];
            ssb[it] += v0.x * v0.x + v0.y * v0.y + v0.z * v0.z + v0.w * v0.w
                     + v1.x * v1.x + v1.y * v1.y + v1.z * v1.z + v1.w * v1.w;
            hB[it * 4 + 0] = pack_h2(v0.x, v0.y); hB[it * 4 + 1] = pack_h2(v0.z, v0.w);
            hB[it * 4 + 2] = pack_h2(v1.x, v1.y); hB[it * 4 + 3] = pack_h2(v1.z, v1.w);
        }
    }

    unsigned* const Abase = sm_u;
    unsigned* const Bbase = sm_u + 2 * 128 * RSTR;

    for (int c = 0; c < NCH; c++) {
        unsigned* Au = Abase + (c & 1) * 128 * RSTR;
        unsigned* Bu = diag ? Au : (Bbase + (c & 1) * 128 * RSTR);

        // store converted chunk c (one STS.128 per row-iter per matrix)
        #pragma unroll
        for (int it = 0; it < 2; it++) {
            unsigned* dA = Au + (it * 64 + frow0) * RSTR + ft4 * 4;
            *(uint4*)dA = make_uint4(hA[it * 4 + 0], hA[it * 4 + 1],
                                     hA[it * 4 + 2], hA[it * 4 + 3]);
            if (!diag) {
                unsigned* dB = Bbase + (c & 1) * 128 * RSTR
                             + (it * 64 + frow0) * RSTR + ft4 * 4;
                *(uint4*)dB = make_uint4(hB[it * 4 + 0], hB[it * 4 + 1],
                                         hB[it * 4 + 2], hB[it * 4 + 3]);
            }
        }
        __syncthreads();

        // prefetch + convert chunk c+1 (overlaps with MMA below)
        if (c + 1 < NCH) {
            int f4o = (c + 1) * 8 + ft4 * 2;
            #pragma unroll
            for (int it = 0; it < 2; it++) {
                if (inbA[it]) {
                    float4 v0 = srcA[it][f4o], v1 = srcA[it][f4o + 1];
                    ssa[it] += v0.x * v0.x + v0.y * v0.y + v0.z * v0.z + v0.w * v0.w
                             + v1.x * v1.x + v1.y * v1.y + v1.z * v1.z + v1.w * v1.w;
                    hA[it * 4 + 0] = pack_h2(v0.x, v0.y); hA[it * 4 + 1] = pack_h2(v0.z, v0.w);
                    hA[it * 4 + 2] = pack_h2(v1.x, v1.y); hA[it * 4 + 3] = pack_h2(v1.z, v1.w);
                }
                if (inbB[it]) {
                    float4 v0 = srcB[it][f4o], v1 = srcB[it][f4o + 1];
                    ssb[it] += v0.x * v0.x + v0.y * v0.y + v0.z * v0.z + v0.w * v0.w
                             + v1.x * v1.x + v1.y * v1.y + v1.z * v1.z + v1.w * v1.w;
                    hB[it * 4 + 0] = pack_h2(v0.x, v0.y); hB[it * 4 + 1] = pack_h2(v0.z, v0.w);
                    hB[it * 4 + 2] = pack_h2(v1.x, v1.y); hB[it * 4 + 3] = pack_h2(v1.z, v1.w);
                }
            }
        }

        // ---- MMA: two k16 steps cover the 32-wide chunk ----
        #pragma unroll
        for (int ks = 0; ks < 2; ks++) {
            int kb = ks * 8 + t4;
            unsigned afr[4][4];
            #pragma unroll
            for (int ma = 0; ma < 4; ma++) {
                int r = wm * 64 + ma * 16 + g4;
                afr[ma][0] = Au[r * RSTR + kb];
                afr[ma][1] = Au[(r + 8) * RSTR + kb];
                afr[ma][2] = Au[r * RSTR + 4 + kb];
                afr[ma][3] = Au[(r + 8) * RSTR + 4 + kb];
            }
            unsigned bfr[4][2];
            #pragma unroll
            for (int na = 0; na < 4; na++) {
                int cidx = wn * 32 + na * 8 + g4;
                bfr[na][0] = Bu[cidx * RSTR + kb];
                bfr[na][1] = Bu[cidx * RSTR + 4 + kb];
            }
            #pragma unroll
            for (int ma = 0; ma < 4; ma++)
                #pragma unroll
                for (int na = 0; na < 4; na++)
                    mma_f16(acc[ma][na], afr[ma], bfr[na]);
        }
        // no trailing barrier: store(c+2) is ordered after barrier(c+1), which
        // all warps reach only after finishing mma(c) -- hazard-free.
    }

    // ---- reduce per-row sum of squares (over the 4-lane row group) ----
    #pragma unroll
    for (int it = 0; it < 2; it++) {
        float s = ssa[it];
        s += __shfl_xor_sync(0xffffffffu, s, 1);
        s += __shfl_xor_sync(0xffffffffu, s, 2);
        if (ft4 == 0) rnA[it * 64 + frow0] = 1.0f / fmaxf(sqrtf(s), 1e-12f);
        if (!diag) {
            float t = ssb[it];
            t += __shfl_xor_sync(0xffffffffu, t, 1);
            t += __shfl_xor_sync(0xffffffffu, t, 2);
            if (ft4 == 0) rnB[it * 64 + frow0] = 1.0f / fmaxf(sqrtf(t), 1e-12f);
        }
    }
    __syncthreads();
    const float* rnBp = diag ? rnA : rnB;

    // ---- epilogue 1: this quadrant's tile (coalesced float2, scaled) ----
    #pragma unroll
    for (int ma = 0; ma < 4; ma++) {
        #pragma unroll
        for (int na = 0; na < 4; na++) {
            int lj = wn * 32 + na * 8 + 2 * t4;
            int gj = j0 + lj;
            if (gj >= NN) continue;
            float rb0 = rnBp[lj], rb1 = rnBp[lj + 1];
            #pragma unroll
            for (int hh = 0; hh < 2; hh++) {
                int li = wm * 64 + ma * 16 + g4 + hh * 8;
                int gi = i0 + li;
                if (gi >= NN) continue;
                float ra = rnA[li];
                float v0 = acc[ma][na][hh * 2 + 0] * ra * rb0;
                float v1 = acc[ma][na][hh * 2 + 1] * ra * rb1;
                if (diag) {
                    if (gi == gj)     v0 = 0.f;
                    if (gi == gj + 1) v1 = 0.f;
                }
                if (v0 > 0.9f) rec_edge(eslot, gi, gj);
                if (v1 > 0.9f && gj + 1 < NN) rec_edge(eslot, gi, gj + 1);
                *(float2*)&sim_out[((size_t)b * NN + gi) * NN + gj] = make_float2(v0, v1);
            }
        }
    }

    // ---- epilogue 2: mirror (1,0) via smem transpose (off-diag CTA only) ----
    if (mirror) {
        float* S = (float*)sm_u;         // 32 x 132 staging (16.9KB <= 40KB)
        #pragma unroll
        for (int cb = 0; cb < 3; cb++) {   // local col chunks; cb=3 all OOB
            __syncthreads();
            if (wn == cb) {
                #pragma unroll
                for (int ma = 0; ma < 4; ma++)
                    #pragma unroll
                    for (int na = 0; na < 4; na++)
                        #pragma unroll
                        for (int q = 0; q < 4; q++) {
                            int jc = na * 8 + 2 * t4 + (q & 1);
                            int il = wm * 64 + ma * 16 + g4 + 8 * (q >> 1);
                            S[jc * 132 + il] = acc[ma][na][q] * rnA[il] * rnBp[cb * 32 + jc];
                        }
            }
            __syncthreads();
            #pragma unroll
            for (int it = 0; it < 4; it++) {
                int jc = it * 8 + (tid >> 5);
                int gj = 128 + cb * 32 + jc;       // mirror row
                if (gj >= NN) continue;
                int i = (tid & 31) * 4;
                float4 v = *(float4*)&S[jc * 132 + i];
                if (v.x > 0.9f) rec_edge(eslot, gj, i + 0);
                if (v.y > 0.9f) rec_edge(eslot, gj, i + 1);
                if (v.z > 0.9f) rec_edge(eslot, gj, i + 2);
                if (v.w > 0.9f) rec_edge(eslot, gj, i + 3);
                *(float4*)&sim_out[((size_t)b * NN + gj) * NN + i] = v;
            }
        }
    }
}

// ---------------- kernel 2: grouping (fused gmax + importance) ---------------
__global__ void __launch_bounds__(256, 1)
group_kernel(const float* __restrict__ m, const float* __restrict__ s,
             const float* __restrict__ sim_in_arg,
             float* out_imp, float* out_gids) {
    int b = blockIdx.x, tid = threadIdx.x;
    const float* sim_in = sim_in_arg ? sim_in_arg : g_sim;
    __shared__ unsigned adj[NN][8];
    __shared__ float simp[NN];
    __shared__ int   sgid[NN];
    __shared__ float denom[NN];
    __shared__ int   cnt[NN];
    __shared__ int   off[NN + 1];
    __shared__ int   cur[NN];
    __shared__ float lo[256], hi[256];
    __shared__ float wr0[8], wr1[8];
    __shared__ unsigned assigned[8], reach[8], nxt[8];
    __shared__ int s_changed, s_ng, s_any;

    // ---- global max of motion / saliency (deterministic per-CTA scan) ----
    float mx0 = 0.f, mx1 = 0.f;
    for (int i = tid; i < NTOK; i += 256) {
        mx0 = fmaxf(mx0, m[i]);
        mx1 = fmaxf(mx1, s[i]);
    }
    #pragma unroll
    for (int o = 16; o; o >>= 1) {
        mx0 = fmaxf(mx0, __shfl_xor_sync(0xffffffffu, mx0, o));
        mx1 = fmaxf(mx1, __shfl_xor_sync(0xffffffffu, mx1, o));
    }
    int lane = tid & 31, warp = tid >> 5;
    if (lane == 0) { wr0[warp] = mx0; wr1[warp] = mx1; }
    __syncthreads();
    float gm0 = wr0[0], gm1 = wr1[0];
    #pragma unroll
    for (int w = 1; w < 8; w++) { gm0 = fmaxf(gm0, wr0[w]); gm1 = fmaxf(gm1, wr1[w]); }

    // ---- importance for this batch ----
    bool valid = (tid < NN);
    float v = 0.f;
    if (valid) {
        float mn = m[b * NN + tid] / (gm0 + EPSF);
        float sn = s[b * NN + tid] / (gm1 + EPSF);
        v = 0.5f * mn + 0.5f * sn;
    }
    lo[tid] = valid ? v :  CUDART_INF_F;
    hi[tid] = valid ? v : -CUDART_INF_F;
    __syncthreads();
    for (int o = 128; o; o >>= 1) {
        if (tid < o) { lo[tid] = fminf(lo[tid], lo[tid + o]); hi[tid] = fmaxf(hi[tid], hi[tid + o]); }
        __syncthreads();
    }
    float l = lo[0], h = hi[0];
    if (valid) {
        float r = (v - l) / (h - l + EPSF);
        simp[tid] = r;
        if (out_imp) out_imp[b * NN + tid] = r;
    }
    for (int i = tid; i < NN; i += 256) { cnt[i] = 0; denom[i] = EPSF; }
    if (tid < 8) assigned[tid] = 0u;
    if (tid == 0) { s_ng = 0; s_any = 0; }
    __syncthreads();

    // ---- adjacency from per-quadrant edge lists ----
    int e0 = g_edge_cnt[b * 3 + 0];
    int e1 = g_edge_cnt[b * 3 + 1];
    int e2 = g_edge_cnt[b * 3 + 2];
    int etot = e0 + e1 + e2;
    bool overflow = (e0 > EMAX3) || (e1 > EMAX3) || (e2 > EMAX3);

    if (etot == 0) {
        for (int i = tid; i < NN; i += 256) sgid[i] = i;
        if (tid == 0) s_ng = NN;
        __syncthreads();
    } else {
        for (int i = tid; i < NN * 8; i += 256) (&adj[0][0])[i] = 0u;
        __syncthreads();
        if (!overflow) {
            #pragma unroll
            for (int q = 0; q < 3; q++) {
                int ec = (q == 0) ? e0 : (q == 1) ? e1 : e2;
                const int* el = &g_edges[(b * 3 + q) * EMAX3];
                for (int e = tid; e < ec; e += 256) {
                    int pk = el[e];
                    int i = pk >> 8, j = pk & 255;
                    if (j < NN && (1.0f - simp[i]) > 0.5f) {
                        atomicOr(&adj[i][j >> 5], 1u << (j & 31));
                        s_any = 1;
                    }
                }
            }
        } else {
            const float* simb = sim_in + (size_t)b * NN * NN;
            for (int idx = tid; idx < NN * NN; idx += 256) {
                int i = idx / NN, j = idx - i * NN;
                float sv = simb[idx];
                if (sv > 0.9f && (1.0f - simp[i]) > 0.5f) {
                    atomicOr(&adj[i][j >> 5], 1u << (j & 31));
                    s_any = 1;
                }
            }
        }
        __syncthreads();

        if (s_any == 0) {
            for (int i = tid; i < NN; i += 256) sgid[i] = i;
            if (tid == 0) s_ng = NN;
            __syncthreads();
        } else {
            for (int r = 0; r < NN; r++) {
                if ((assigned[r >> 5] >> (r & 31)) & 1u) continue;
                if (tid < 8) reach[tid] = (tid == (r >> 5)) ? (1u << (r & 31)) : 0u;
                __syncthreads();
                while (true) {
                    if (tid < 8) nxt[tid] = 0u;
                    if (tid == 0) s_changed = 0;
                    __syncthreads();
                    for (int i = tid; i < NN; i += 256) {
                        if ((reach[i >> 5] >> (i & 31)) & 1u) {
                            #pragma unroll
                            for (int w = 0; w < 7; w++) {
                                unsigned vv = adj[i][w];
                                if (vv) atomicOr(&nxt[w], vv);
                            }
                        }
                    }
                    __syncthreads();
                    if (tid < 8) {
                        unsigned nv = reach[tid] | (nxt[tid] & ~assigned[tid]);
                        if (nv != reach[tid]) s_changed = 1;
                        nxt[tid] = nv;
                    }
                    __syncthreads();
                    if (tid < 8) reach[tid] = nxt[tid];
                    __syncthreads();
                    if (!s_changed) break;
                }
                int gid = s_ng;
                for (int i = tid; i < NN; i += 256)
                    if ((reach[i >> 5] >> (i & 31)) & 1u) sgid[i] = gid;
                if (tid < 8) assigned[tid] |= reach[tid];
                __syncthreads();
                if (tid == 0) s_ng = gid + 1;
                __syncthreads();
            }
        }
    }

    // ---- weights + CSR ----
    for (int i = tid; i < NN; i += 256) atomicAdd(&denom[sgid[i]], simp[i]);
    __syncthreads();
    for (int i = tid; i < NN; i += 256) {
        g_w[b * NN + i] = simp[i] / denom[sgid[i]];
        if (out_gids) out_gids[b * NN + i] = (float)sgid[i];
        atomicAdd(&cnt[sgid[i]], 1);
    }
    __syncthreads();
    if (tid == 0) {
        off[0] = 0;
        for (int g = 0; g < NN; g++) off[g + 1] = off[g] + cnt[g];
    }
    __syncthreads();
    for (int g = tid; g < NN; g += 256) cur[g] = off[g];
    for (int g = tid; g < NN + 1; g += 256) g_goff[b * (NN + 1) + g] = off[g];
    __syncthreads();
    for (int i = tid; i < NN; i += 256) {
        int g = sgid[i];
        int pos = atomicAdd(&cur[g], 1);
        g_members[b * NN + pos] = i;
    }
}

// ---------------- kernel 3: merged tokens (CSR gather, float4) ----------------
__global__ void __launch_bounds__(192)
merge_kernel(const float* __restrict__ tok, float* __restrict__ out) {
    int b = blockIdx.y, g = blockIdx.x, tid = threadIdx.x;
    int o0 = g_goff[b * (NN + 1) + g];
    int o1 = g_goff[b * (NN + 1) + g + 1];
    float4 a = make_float4(0.f, 0.f, 0.f, 0.f);
    const float4* tokb = (const float4*)(tok + (size_t)b * NN * DD);
    for (int k = o0; k < o1; k++) {
        int i = g_members[b * NN + k];
        float wv = g_w[b * NN + i];
        float4 v = tokb[(size_t)i * (DD / 4) + tid];
        a.x += v.x * wv; a.y += v.y * wv; a.z += v.z * wv; a.w += v.w * wv;
    }
    ((float4*)out)[((size_t)b * NN + g) * (DD / 4) + tid] = a;
}

// ---------------- launch ------------------------------------------------------
extern "C" void kernel_launch(void* const* d_in, const int* in_sizes, int n_in,
                              void* d_out, int out_size) {
    const float* tokens = (const float*)d_in[0];
    const float* motion = (const float*)d_in[1];
    const float* sal    = (const float*)d_in[2];
    float* out = (float*)d_out;

    const long long SZ_M = (long long)BB * NN * DD;   // 19267584
    const long long SZ_S = (long long)BB * NN * NN;   //  4917248
    const long long SZ_I = (long long)BB * NN;        //    25088
    long long osz = (long long)out_size;

    float* out_sim  = (osz >= SZ_M + SZ_S)            ? out + SZ_M               : nullptr;
    float* out_imp  = (osz >= SZ_M + SZ_S + SZ_I)     ? out + SZ_M + SZ_S        : nullptr;
    float* out_gids = (osz >= SZ_M + SZ_S + 2 * SZ_I) ? out + SZ_M + SZ_S + SZ_I : nullptr;

    sim_kernel<<<dim3(3, BB), 256>>>(tokens, out_sim);
    group_kernel<<<BB, 256>>>(motion, sal, out_sim, out_imp, out_gids);
    merge_kernel<<<dim3(NN, BB), 192>>>(tokens, out);
}